// round 16
// baseline (speedup 1.0000x reference)
#include <cuda_runtime.h>
#include <cuda_bf16.h>
#include <math.h>

#define MAXN   2048
#define NW     (MAXN / 64)
#define OUT_N  1000
#define FULLW  0xffffffffu
#define MAXE   16384
#define MAXC   262144
#define NCX    16
#define CINV   (1.0f / 64.0f)

// ---------------- device scratch ----------------
__device__ int          g_order[MAXN];
__device__ float2       g_pts[MAXN][4];
__device__ float4       g_meta[MAXN];       // x, y, area, circumradius
__device__ float4       g_aabb[MAXN];       // xmin, ymin, xmax, ymax
__device__ int          g_cellStart[NCX * NCX + 1];
__device__ int          g_cellIds[MAXN];
__device__ float        g_rmax;
__device__ int          g_ccnt;
__device__ unsigned int g_cand[MAXC];
__device__ int          g_ecnt;
__device__ unsigned int g_edges[MAXE];

// ---------------- kernel 1: fused stable rank + corners + aabb ---------------
__global__ void rank_corner_kernel(const float* __restrict__ scores,
                                   const float* __restrict__ boxes, int n) {
    int i = blockIdx.x;
    if (i == 0 && threadIdx.x == 0) { g_ccnt = 0; g_ecnt = 0; }
    if (i >= n) return;
    float s = scores[i];
    int t = threadIdx.x;
    int cnt = 0;
    for (int j = t; j < n; j += 256) {
        float sj = scores[j];
        cnt += (sj > s) || (sj == s && j < i);
    }
    __shared__ int red[256];
    red[t] = cnt;
    __syncthreads();
    for (int o = 128; o > 0; o >>= 1) {
        if (t < o) red[t] += red[t + o];
        __syncthreads();
    }
    if (t == 0) {
        int k = red[0];
        g_order[k] = i;
        float xc = boxes[i * 5 + 0];
        float yc = boxes[i * 5 + 1];
        float w  = boxes[i * 5 + 2];
        float h  = boxes[i * 5 + 3];
        float th = boxes[i * 5 + 4];
        float a = th * 0.017453292519943295f;
        float c = cosf(a), sn = sinf(a);
        float dx = w * 0.5f, dy = h * 0.5f;
        const float lx[4] = { -dx, dx, dx, -dx };
        const float ly[4] = { -dy, -dy, dy, dy };
        float xmn = 1e30f, ymn = 1e30f, xmx = -1e30f, ymx = -1e30f;
#pragma unroll
        for (int e = 0; e < 4; e++) {
            float px = xc + lx[e] * c - ly[e] * sn;
            float py = yc + lx[e] * sn + ly[e] * c;
            g_pts[k][e] = make_float2(px, py);
            xmn = fminf(xmn, px); xmx = fmaxf(xmx, px);
            ymn = fminf(ymn, py); ymx = fmaxf(ymx, py);
        }
        g_meta[k] = make_float4(xc, yc, w * h, 0.5f * sqrtf(w * w + h * h));
        g_aabb[k] = make_float4(xmn, ymn, xmx, ymx);
    }
}

// ---------------- kernel 2: spatial binning (single block) -------------------
__global__ void bin_kernel(int n) {
    __shared__ int cnt[256], cnt2[256], off[256];
    __shared__ int wsum[8];
    __shared__ int rmaxI;
    int tid = threadIdx.x;               // 256 threads
    cnt[tid] = 0; cnt2[tid] = 0;
    if (tid == 0) rmaxI = 0;
    __syncthreads();

    float rm = 0.0f;
    for (int k = tid; k < n; k += 256) {
        float4 m = g_meta[k];
        int cx = min(15, max(0, (int)(m.x * CINV)));
        int cy = min(15, max(0, (int)(m.y * CINV)));
        atomicAdd(&cnt[cy * 16 + cx], 1);
        rm = fmaxf(rm, m.w);
    }
    atomicMax(&rmaxI, __float_as_int(rm));   // rm >= 0: int order == float order
    __syncthreads();

    // two-level exclusive scan of cnt[256]
    int lane = tid & 31, wp = tid >> 5;
    int v = cnt[tid];
    int s = v;
#pragma unroll
    for (int o = 1; o < 32; o <<= 1) {
        int tt = __shfl_up_sync(FULLW, s, o);
        if (lane >= o) s += tt;
    }
    if (lane == 31) wsum[wp] = s;
    __syncthreads();
    if (tid == 0) {
        int acc = 0;
        for (int w = 0; w < 8; w++) { int tt = wsum[w]; wsum[w] = acc; acc += tt; }
    }
    __syncthreads();
    off[tid] = s - v + wsum[wp];
    __syncthreads();
    g_cellStart[tid] = off[tid];
    if (tid == 0) { g_cellStart[256] = n; g_rmax = __int_as_float(rmaxI); }

    for (int k = tid; k < n; k += 256) {
        float4 m = g_meta[k];
        int cx = min(15, max(0, (int)(m.x * CINV)));
        int cy = min(15, max(0, (int)(m.y * CINV)));
        int c = cy * 16 + cx;
        int slot = off[c] + atomicAdd(&cnt2[c], 1);
        g_cellIds[slot] = k;
    }
}

// ---------------- kernel 3: windowed pair generation (2 threads / box) -------
__global__ void pairgen_kernel(int n) {
    int T = blockIdx.x * blockDim.x + threadIdx.x;
    int i = T >> 1, h = T & 1;
    if (i >= n) return;
    float4 mi = g_meta[i];
    float4 bi = g_aabb[i];
    float reach = mi.w + g_rmax + 0.5f;
    int cx0 = max(0,  (int)floorf((mi.x - reach) * CINV));
    int cx1 = min(15, (int)floorf((mi.x + reach) * CINV));
    int cy0 = max(0,  (int)floorf((mi.y - reach) * CINV));
    int cy1 = min(15, (int)floorf((mi.y + reach) * CINV));

    for (int cy = cy0 + h; cy <= cy1; cy += 2) {
        for (int cx = cx0; cx <= cx1; cx++) {
            int c = cy * 16 + cx;
            int s0 = g_cellStart[c], s1 = g_cellStart[c + 1];
            for (int s = s0; s < s1; s++) {
                int j = g_cellIds[s];
                if (j <= i) continue;
                float4 mj = g_meta[j];
                float ddx = mi.x - mj.x, ddy = mi.y - mj.y;
                float rr  = mi.w + mj.w;
                if (ddx * ddx + ddy * ddy > rr * rr) continue;     // disjoint
                float amin = fminf(mi.z, mj.z), amax = fmaxf(mi.z, mj.z);
                if (amin <= 0.695f * amax) continue;               // ratio bound
                float4 bj = g_aabb[j];
                float ix = fminf(bi.z, bj.z) - fmaxf(bi.x, bj.x);
                float iy = fminf(bi.w, bj.w) - fmaxf(bi.y, bj.y);
                if (ix <= 0.0f || iy <= 0.0f) continue;            // AABB disjoint
                float ain = ix * iy;                               // inter upper bound
                if (1.695f * ain <= 0.695f * (mi.z + mj.z)) continue; // IoU bound < 0.7
                int pos = atomicAdd(&g_ccnt, 1);
                if (pos < MAXC) g_cand[pos] = ((unsigned)i << 11) | (unsigned)j;
            }
        }
    }
}

// ---------------- Sutherland-Hodgman quad-quad intersection area -------------
__device__ __forceinline__ float inter_area(const float2 A[4], const float2 B[4]) {
    float px[8], py[8];
#pragma unroll
    for (int k = 0; k < 4; k++) { px[k] = A[k].x; py[k] = A[k].y; }
    int cnt = 4;
#pragma unroll
    for (int e = 0; e < 4; e++) {
        float ax = B[e].x, ay = B[e].y;
        float bx = B[(e + 1) & 3].x, by = B[(e + 1) & 3].y;
        float ex = bx - ax, ey = by - ay;
        float d[8];
#pragma unroll
        for (int k = 0; k < 8; k++)
            d[k] = (k < cnt) ? (ex * (py[k] - ay) - ey * (px[k] - ax)) : 0.0f;
        float ox[8], oy[8];
        int oc = 0;
#pragma unroll
        for (int k = 0; k < 8; k++) {
            if (k < cnt) {
                int kn = (k + 1 < cnt) ? k + 1 : 0;
                bool ic  = d[k]  >= 0.0f;
                bool in_ = d[kn] >= 0.0f;
                if (ic && oc < 8) { ox[oc] = px[k]; oy[oc] = py[k]; oc++; }
                if ((ic != in_) && oc < 8) {
                    float den = d[k] - d[kn];
                    float tp = (fabsf(den) > 1e-12f) ? (d[k] / den) : 0.0f;
                    ox[oc] = px[k] + tp * (px[kn] - px[k]);
                    oy[oc] = py[k] + tp * (py[kn] - py[k]);
                    oc++;
                }
            }
        }
        cnt = oc;
#pragma unroll
        for (int k = 0; k < 8; k++)
            if (k < cnt) { px[k] = ox[k]; py[k] = oy[k]; }
    }
    float ar = 0.0f;
#pragma unroll
    for (int k = 0; k < 8; k++) {
        if (k < cnt) {
            int kn = (k + 1 < cnt) ? k + 1 : 0;
            ar += px[k] * py[kn] - px[kn] * py[k];
        }
    }
    return fmaxf(0.5f * ar, 0.0f);
}

// ---------------- kernel 4: clip candidates, emit suppression edges ----------
__global__ void clip_kernel() {
    int C = g_ccnt; if (C > MAXC) C = MAXC;
    for (int idx = blockIdx.x * blockDim.x + threadIdx.x; idx < C;
         idx += gridDim.x * blockDim.x) {
        unsigned k = g_cand[idx];
        int i = k >> 11, j = k & 2047;
        float2 A[4], B[4];
#pragma unroll
        for (int e = 0; e < 4; e++) { A[e] = g_pts[i][e]; B[e] = g_pts[j][e]; }
        float inter = inter_area(A, B);
        float u = fmaxf(g_meta[i].z + g_meta[j].z - inter, 1e-9f);
        if (inter / u > 0.7f) {
            int p = atomicAdd(&g_ecnt, 1);
            if (p < MAXE) g_edges[p] = k;
        }
    }
}

// ---------------- kernel 5: fixpoint greedy + emission -----------------------
// Alternating bounds S_lo ⊆ SUP ⊆ S_hi converge exactly to the greedy result.
__global__ void reduce_kernel(int n, float* __restrict__ out) {
    __shared__ unsigned long long slo[NW], shi[NW], tmp[NW];
    __shared__ int neq;
    int tid = threadIdx.x;              // 128 threads
    int E = g_ecnt; if (E > MAXE) E = MAXE;

    if (tid < NW) { slo[tid] = 0ULL; shi[tid] = ~0ULL; }
    __syncthreads();

    for (int round = 0; round < 4096; round++) {
        // grow S_lo: i certainly kept (i ∉ S_hi) suppresses j for sure
        for (int e = tid; e < E; e += 128) {
            unsigned k = g_edges[e];
            int i = k >> 11, j = k & 2047;
            if (!((shi[i >> 6] >> (i & 63)) & 1ULL))
                atomicOr(&slo[j >> 6], 1ULL << (j & 63));
        }
        if (tid < NW) tmp[tid] = 0ULL;
        if (tid == 0) neq = 0;
        __syncthreads();
        // recompute S_hi: j possibly suppressed iff some i possibly kept
        for (int e = tid; e < E; e += 128) {
            unsigned k = g_edges[e];
            int i = k >> 11, j = k & 2047;
            if (!((slo[i >> 6] >> (i & 63)) & 1ULL))
                atomicOr(&tmp[j >> 6], 1ULL << (j & 63));
        }
        __syncthreads();
        if (tid < NW) {
            shi[tid] = tmp[tid];
            if (tmp[tid] != slo[tid]) atomicAdd(&neq, 1);
        }
        __syncthreads();
        if (neq == 0) break;
    }

    // Emission: warp 0 prefix-scans keep-counts; sup == slo at fixpoint
    if (tid < 32) {
        const int L  = tid;
        const int nw = (n + 63) / 64;
        unsigned long long kw = 0ULL;
        if (L < nw) {
            int rem = n - L * 64;
            unsigned long long validm = (rem >= 64) ? ~0ULL : ((1ULL << rem) - 1ULL);
            kw = ~slo[L] & validm;
        }
        int pc = __popcll(kw);
        int sc = pc;
#pragma unroll
        for (int o = 1; o < 32; o <<= 1) {
            int vv = __shfl_up_sync(FULLW, sc, o);
            if (L >= o) sc += vv;
        }
        int excl = sc - pc;
        while (kw) {
            int b = __ffsll((long long)kw) - 1;
            kw &= kw - 1ULL;
            if (excl < OUT_N) out[excl] = (float)g_order[L * 64 + b];
            excl++;
        }
        int kept = __shfl_sync(FULLW, sc, 31);
        for (int p = kept + L; p < OUT_N; p += 32) out[p] = -1.0f;
    }
}

// ---------------- launch -----------------------------------------------------
extern "C" void kernel_launch(void* const* d_in, const int* in_sizes, int n_in,
                              void* d_out, int out_size) {
    const float* boxes;
    const float* scores;
    int n;
    if (n_in >= 2 && in_sizes[0] == 5 * in_sizes[1]) {
        boxes = (const float*)d_in[0]; scores = (const float*)d_in[1]; n = in_sizes[1];
    } else if (n_in >= 2 && in_sizes[1] == 5 * in_sizes[0]) {
        boxes = (const float*)d_in[1]; scores = (const float*)d_in[0]; n = in_sizes[0];
    } else {
        boxes = (const float*)d_in[0]; scores = (const float*)d_in[1]; n = in_sizes[1];
    }
    if (n > MAXN) n = MAXN;
    float* out = (float*)d_out;

    rank_corner_kernel<<<n, 256>>>(scores, boxes, n);
    bin_kernel<<<1, 256>>>(n);
    pairgen_kernel<<<(2 * n + 255) / 256, 256>>>(n);
    clip_kernel<<<128, 128>>>();
    reduce_kernel<<<1, 128>>>(n, out);
}

// round 17
// speedup vs baseline: 3.7234x; 3.7234x over previous
#include <cuda_runtime.h>
#include <cuda_bf16.h>
#include <math.h>

#define MAXN   2048
#define NW     (MAXN / 64)
#define OUT_N  1000
#define FULLW  0xffffffffu
#define MAXE   16384

// ---------------- device scratch ----------------
__device__ int          g_order[MAXN];
__device__ float2       g_pts[MAXN][4];
__device__ float4       g_meta[MAXN];       // x, y, area, circumradius
__device__ int          g_ecnt;
__device__ unsigned int g_edges[MAXE];      // (i<<11)|j, sorted space, i<j

// ---------------- kernel 1: rank (8 warps/block, smem scores) + corners ------
__global__ void rank_corner_kernel(const float* __restrict__ scores,
                                   const float* __restrict__ boxes, int n) {
    __shared__ float ss[MAXN];
    const int tid  = threadIdx.x;            // 256 threads
    const int wp   = tid >> 5;
    const int lane = tid & 31;

    if (blockIdx.x == 0 && tid == 0) g_ecnt = 0;

    // Stage all scores in shared (coalesced, 8 per thread)
    for (int j = tid; j < n; j += 256) ss[j] = scores[j];
    __syncthreads();

    const int i = blockIdx.x * 8 + wp;       // one box per warp
    if (i >= n) return;
    const float s = ss[i];

    int cnt = 0;
    for (int k = lane; k < n; k += 32) {
        float sj = ss[k];
        cnt += (sj > s) || (sj == s && k < i);
    }
#pragma unroll
    for (int o = 16; o; o >>= 1) cnt += __shfl_xor_sync(FULLW, cnt, o);

    if (lane == 0) {
        int k = cnt;
        g_order[k] = i;
        float xc = boxes[i * 5 + 0];
        float yc = boxes[i * 5 + 1];
        float w  = boxes[i * 5 + 2];
        float h  = boxes[i * 5 + 3];
        float th = boxes[i * 5 + 4];
        float a = th * 0.017453292519943295f;
        float c = cosf(a), sn = sinf(a);
        float dx = w * 0.5f, dy = h * 0.5f;
        const float lx[4] = { -dx, dx, dx, -dx };
        const float ly[4] = { -dy, -dy, dy, dy };
#pragma unroll
        for (int e = 0; e < 4; e++) {
            g_pts[k][e] = make_float2(xc + lx[e] * c - ly[e] * sn,
                                      yc + lx[e] * sn + ly[e] * c);
        }
        g_meta[k] = make_float4(xc, yc, w * h, 0.5f * sqrtf(w * w + h * h));
    }
}

// ---------------- Sutherland-Hodgman quad-quad intersection area -------------
__device__ __forceinline__ float inter_area(const float2 A[4], const float2 B[4]) {
    float px[8], py[8];
#pragma unroll
    for (int k = 0; k < 4; k++) { px[k] = A[k].x; py[k] = A[k].y; }
    int cnt = 4;
#pragma unroll
    for (int e = 0; e < 4; e++) {
        float ax = B[e].x, ay = B[e].y;
        float bx = B[(e + 1) & 3].x, by = B[(e + 1) & 3].y;
        float ex = bx - ax, ey = by - ay;
        float d[8];
#pragma unroll
        for (int k = 0; k < 8; k++)
            d[k] = (k < cnt) ? (ex * (py[k] - ay) - ey * (px[k] - ax)) : 0.0f;
        float ox[8], oy[8];
        int oc = 0;
#pragma unroll
        for (int k = 0; k < 8; k++) {
            if (k < cnt) {
                int kn = (k + 1 < cnt) ? k + 1 : 0;
                bool ic  = d[k]  >= 0.0f;
                bool in_ = d[kn] >= 0.0f;
                if (ic && oc < 8) { ox[oc] = px[k]; oy[oc] = py[k]; oc++; }
                if ((ic != in_) && oc < 8) {
                    float den = d[k] - d[kn];
                    float tp = (fabsf(den) > 1e-12f) ? (d[k] / den) : 0.0f;
                    ox[oc] = px[k] + tp * (px[kn] - px[k]);
                    oy[oc] = py[k] + tp * (py[kn] - py[k]);
                    oc++;
                }
            }
        }
        cnt = oc;
#pragma unroll
        for (int k = 0; k < 8; k++)
            if (k < cnt) { px[k] = ox[k]; py[k] = oy[k]; }
    }
    float ar = 0.0f;
#pragma unroll
    for (int k = 0; k < 8; k++) {
        if (k < cnt) {
            int kn = (k + 1 < cnt) ? k + 1 : 0;
            ar += px[k] * py[kn] - px[kn] * py[k];
        }
    }
    return fmaxf(0.5f * ar, 0.0f);
}

// ---------------- kernel 2: 64x64 tile, prune->compact->clip->edge append ----
__global__ void mask_kernel(int n) {
    const int rb = blockIdx.y, cb = blockIdx.x, t = threadIdx.x;  // 128 threads
    if (cb < rb) return;                  // upper triangle only

    __shared__ float2 sP[64][4];
    __shared__ float4 sM[64];
    __shared__ unsigned short q[4096];
    __shared__ int qcnt;

    if (t == 0) qcnt = 0;
    if (t < 64) {
        int j = cb * 64 + t;
        if (j < n) {
            sM[t] = g_meta[j];
#pragma unroll
            for (int e = 0; e < 4; e++) sP[t][e] = g_pts[j][e];
        } else {
            sM[t] = make_float4(1e30f, 1e30f, 0.0f, 0.0f);
        }
    }
    __syncthreads();

    // Phase 1: each thread prunes one (row, col-half): 32 candidates
    {
        int r = t >> 1, half = t & 1;
        int i = rb * 64 + r;
        if (i < n) {
            float4 mi = g_meta[i];
            int c0 = half * 32;
            for (int cc = c0; cc < c0 + 32; cc++) {
                int j = cb * 64 + cc;
                if (j >= n) break;
                if (cb == rb && cc <= r) continue;               // only j > i
                float4 mj = sM[cc];
                float ddx = mi.x - mj.x, ddy = mi.y - mj.y;
                float rr  = mi.w + mj.w;
                if (ddx * ddx + ddy * ddy > rr * rr) continue;   // disjoint (exact)
                float amin = fminf(mi.z, mj.z), amax = fmaxf(mi.z, mj.z);
                if (amin <= 0.695f * amax) continue;             // IoU < 0.7 bound
                int pos = atomicAdd(&qcnt, 1);
                if (pos < 4096) q[pos] = (unsigned short)((r << 6) | cc);
            }
        }
    }
    __syncthreads();

    // Phase 2: dense clipping over compacted queue; append suppression edges
    int cnt = qcnt > 4096 ? 4096 : qcnt;
    for (int k = t; k < cnt; k += 128) {
        unsigned short pc = q[k];
        int r = pc >> 6, c = pc & 63;
        int ii = rb * 64 + r;
        int jj = cb * 64 + c;
        float2 A[4];
#pragma unroll
        for (int e = 0; e < 4; e++) A[e] = g_pts[ii][e];
        float inter = inter_area(A, sP[c]);
        float aA = g_meta[ii].z, aB = sM[c].z;
        float u = fmaxf(aA + aB - inter, 1e-9f);
        if (inter / u > 0.7f) {
            int pos = atomicAdd(&g_ecnt, 1);
            if (pos < MAXE) g_edges[pos] = ((unsigned)ii << 11) | (unsigned)jj;
        }
    }
}

// ---------------- kernel 3: fixpoint greedy (unsorted edges) + emission ------
// Alternating bounds S_lo ⊆ SUP ⊆ S_hi; edges form a DAG (i<j) so this
// converges exactly to the sequential greedy in ≤ depth rounds.
__global__ void reduce_kernel(int n, float* __restrict__ out) {
    __shared__ unsigned long long slo[NW], shi[NW], tmp[NW];
    __shared__ int neq;
    int tid = threadIdx.x;              // 256 threads
    int E = g_ecnt; if (E > MAXE) E = MAXE;

    if (tid < NW) { slo[tid] = 0ULL; shi[tid] = ~0ULL; }
    __syncthreads();

    for (int round = 0; round < 2048; round++) {
        for (int e = tid; e < E; e += 256) {
            unsigned k = g_edges[e];
            int i = k >> 11, j = k & 2047;
            if (!((shi[i >> 6] >> (i & 63)) & 1ULL))          // i certainly kept
                atomicOr(&slo[j >> 6], 1ULL << (j & 63));
        }
        if (tid < NW) tmp[tid] = 0ULL;
        if (tid == 0) neq = 0;
        __syncthreads();
        for (int e = tid; e < E; e += 256) {
            unsigned k = g_edges[e];
            int i = k >> 11, j = k & 2047;
            if (!((slo[i >> 6] >> (i & 63)) & 1ULL))          // i possibly kept
                atomicOr(&tmp[j >> 6], 1ULL << (j & 63));
        }
        __syncthreads();
        if (tid < NW) {
            shi[tid] = tmp[tid];
            if (tmp[tid] != slo[tid]) atomicAdd(&neq, 1);
        }
        __syncthreads();
        if (neq == 0) break;
    }

    // Emission: warp 0 prefix-scans keep-counts; SUP == slo at fixpoint
    if (tid < 32) {
        const int L  = tid;
        const int nw = (n + 63) / 64;
        unsigned long long kw = 0ULL;
        if (L < nw) {
            int rem = n - L * 64;
            unsigned long long validm = (rem >= 64) ? ~0ULL : ((1ULL << rem) - 1ULL);
            kw = ~slo[L] & validm;
        }
        int pc = __popcll(kw);
        int sc = pc;
#pragma unroll
        for (int o = 1; o < 32; o <<= 1) {
            int vv = __shfl_up_sync(FULLW, sc, o);
            if (L >= o) sc += vv;
        }
        int excl = sc - pc;
        while (kw) {
            int b = __ffsll((long long)kw) - 1;
            kw &= kw - 1ULL;
            if (excl < OUT_N) out[excl] = (float)g_order[L * 64 + b];
            excl++;
        }
        int kept = __shfl_sync(FULLW, sc, 31);
        for (int p = kept + L; p < OUT_N; p += 32) out[p] = -1.0f;
    }
}

// ---------------- launch -----------------------------------------------------
extern "C" void kernel_launch(void* const* d_in, const int* in_sizes, int n_in,
                              void* d_out, int out_size) {
    const float* boxes;
    const float* scores;
    int n;
    if (n_in >= 2 && in_sizes[0] == 5 * in_sizes[1]) {
        boxes = (const float*)d_in[0]; scores = (const float*)d_in[1]; n = in_sizes[1];
    } else if (n_in >= 2 && in_sizes[1] == 5 * in_sizes[0]) {
        boxes = (const float*)d_in[1]; scores = (const float*)d_in[0]; n = in_sizes[0];
    } else {
        boxes = (const float*)d_in[0]; scores = (const float*)d_in[1]; n = in_sizes[1];
    }
    if (n > MAXN) n = MAXN;
    float* out = (float*)d_out;
    int nw = (n + 63) / 64;

    rank_corner_kernel<<<(n + 7) / 8, 256>>>(scores, boxes, n);
    mask_kernel<<<dim3(nw, nw), 128>>>(n);
    reduce_kernel<<<1, 256>>>(n, out);
}